// round 7
// baseline (speedup 1.0000x reference)
#include <cuda_runtime.h>
#include <cuda_bf16.h>
#include <cstdint>

#define BATCH 8
#define T 1024
#define DIM 512
#define IDIM 1024
#define M_ROWS (BATCH * T)   // 8192
#define NBLK 128             // persistent chain grid (<= SM count, single wave)

// ---------------- scratch (static device globals; no allocation) ----------------
__device__ float g_hT[M_ROWS * DIM];      // conv0 output, [b*T+t][d]
__device__ float g_hj[M_ROWS * IDIM];     // join output
__device__ float g_u0[M_ROWS * IDIM];     // ih0 projection (incl. b_ih0)
__device__ float g_hall0[M_ROWS * IDIM];  // h0 for all t
__device__ float g_v1[M_ROWS * IDIM];     // ih1 projection of h0 (incl. b_ih1)
__device__ float g_hall1[M_ROWS * IDIM];  // h1 (= ys) for all t
__device__ float g_y1[M_ROWS * IDIM];     // unjoin mlp1
__device__ float g_y2[M_ROWS * DIM];      // unjoin mlp2, [b*T+t][d]
__device__ float g_st0a[IDIM * BATCH];    // chain state ping-pong ([i*8+b] fp32)
__device__ float g_st0b[IDIM * BATCH];
__device__ float g_st1a[IDIM * BATCH];
__device__ float g_st1b[IDIM * BATCH];
__device__ unsigned g_ctr[2];             // global barrier counters (one per chain)

__device__ __forceinline__ float gelu_f(float v) {
    return 0.5f * v * (1.0f + erff(v * 0.70710678118654752f));
}

// ---------------- init: reset barrier counters, broadcast starter state ----------------
__global__ void init_kernel(const float* __restrict__ starter) {
    int idx = blockIdx.x * blockDim.x + threadIdx.x;
    if (idx < IDIM * BATCH) {
        g_st0a[idx] = starter[idx >> 3];          // [i*8+b] <- starter[0][i]
        g_st1a[idx] = starter[IDIM + (idx >> 3)]; // starter[1][i]
    }
    if (idx < 2) g_ctr[idx] = 0u;
}

// ---------------- depthwise conv 7 + gelu, write transposed [b*T+t][d] ----------------
__global__ void conv0_kernel(const float* __restrict__ x,
                             const float* __restrict__ w,
                             const float* __restrict__ bb) {
    const int idx = blockIdx.x * blockDim.x + threadIdx.x;  // (b,d,t), t fastest
    const int t = idx & (T - 1);
    const int d = (idx >> 10) & (DIM - 1);
    const int b = idx >> 19;
    const float* xr = x + ((size_t)(b * DIM + d) << 10);
    const float* wd = w + d * 7;
    float acc = bb[d];
#pragma unroll
    for (int k = 0; k < 7; k++) {
        const int tt = t + k - 3;
        if (tt >= 0 && tt < T) acc += wd[k] * xr[tt];
    }
    g_hT[((size_t)((b << 10) + t)) * DIM + d] = gelu_f(acc);
}

// ---------------- final depthwise conv 7 + bias + residual ----------------
__global__ void conv1_kernel(const float* __restrict__ x,
                             const float* __restrict__ w,
                             const float* __restrict__ bb,
                             float* __restrict__ out) {
    const int idx = blockIdx.x * blockDim.x + threadIdx.x;  // (b,d,t), t fastest
    const int t = idx & (T - 1);
    const int d = (idx >> 10) & (DIM - 1);
    const int b = idx >> 19;
    const float* wd = w + d * 7;
    float acc = bb[d];
#pragma unroll
    for (int k = 0; k < 7; k++) {
        const int tt = t + k - 3;
        if (tt >= 0 && tt < T)
            acc += wd[k] * g_y2[((size_t)((b << 10) + tt)) * DIM + d];
    }
    out[idx] = x[idx] + acc;
}

// ---------------- fp32 NT GEMM: C[M,N] = act(A[M,K] * W[N,K]^T + bias[N]) ----------------
// 128x128 tile, BK=8, 256 threads, 8x8 per thread. M=8192, N/K in {512,1024}: all divisible.
__global__ void __launch_bounds__(256) gemm_nt(
    const float* __restrict__ A, const float* __restrict__ W,
    const float* __restrict__ bias, float* __restrict__ C,
    int N, int K, int act) {
    __shared__ float As[8][128];
    __shared__ float Ws[8][128];
    const int tid = threadIdx.x;
    const int tx = tid & 15;
    const int ty = tid >> 4;
    const size_t row0 = (size_t)blockIdx.y << 7;
    const int col0 = blockIdx.x << 7;
    const int lrow = tid >> 1;
    const int lk = (tid & 1) << 2;
    const float* Ap = A + (row0 + lrow) * K + lk;
    const float* Wp = W + (size_t)(col0 + lrow) * K + lk;

    float acc[8][8];
#pragma unroll
    for (int i = 0; i < 8; i++)
#pragma unroll
        for (int j = 0; j < 8; j++) acc[i][j] = 0.f;

    for (int k0 = 0; k0 < K; k0 += 8) {
        const float4 av = *(const float4*)(Ap + k0);
        const float4 wv = *(const float4*)(Wp + k0);
        As[lk + 0][lrow] = av.x; As[lk + 1][lrow] = av.y;
        As[lk + 2][lrow] = av.z; As[lk + 3][lrow] = av.w;
        Ws[lk + 0][lrow] = wv.x; Ws[lk + 1][lrow] = wv.y;
        Ws[lk + 2][lrow] = wv.z; Ws[lk + 3][lrow] = wv.w;
        __syncthreads();
#pragma unroll
        for (int kk = 0; kk < 8; kk++) {
            float a[8], w[8];
            *(float4*)&a[0] = *(const float4*)&As[kk][(ty << 3)];
            *(float4*)&a[4] = *(const float4*)&As[kk][(ty << 3) + 4];
            *(float4*)&w[0] = *(const float4*)&Ws[kk][(tx << 3)];
            *(float4*)&w[4] = *(const float4*)&Ws[kk][(tx << 3) + 4];
#pragma unroll
            for (int i = 0; i < 8; i++)
#pragma unroll
                for (int j = 0; j < 8; j++) acc[i][j] += a[i] * w[j];
        }
        __syncthreads();
    }

    float bs[8];
    *(float4*)&bs[0] = *(const float4*)&bias[col0 + (tx << 3)];
    *(float4*)&bs[4] = *(const float4*)&bias[col0 + (tx << 3) + 4];
#pragma unroll
    for (int i = 0; i < 8; i++) {
        const size_t r = row0 + (ty << 3) + i;
        float o[8];
#pragma unroll
        for (int j = 0; j < 8; j++) {
            float v = acc[i][j] + bs[j];
            o[j] = act ? gelu_f(v) : v;
        }
        *(float4*)&C[r * N + col0 + (tx << 3)]     = *(float4*)&o[0];
        *(float4*)&C[r * N + col0 + (tx << 3) + 4] = *(float4*)&o[4];
    }
}

// ---------------- persistent RNN chain: h_t = tanh(U_t + h_{t-1} * Wr^T + bias) ----------------
// 128 CTAs x 8 warps = 1024 warps; warp g owns output row j=g, holding Wr[j][:] in 32 regs.
// Per step: CTA copies the 8x1024 fp32 state (global, double-buffered) into smem as bf16
// ([i][b] packed, 16B per i), every warp dots its row against all 8 batches, butterfly-
// reduces 8 partials, lanes 0..7 finalize tanh and write hall + next-state; then a
// monotonic atomic global barrier (all CTAs single-wave resident => no deadlock).
__global__ void __launch_bounds__(256) chain_kernel(
    const float* __restrict__ Wr, const float* __restrict__ U,
    const float* __restrict__ bias,
    float* __restrict__ stA, float* __restrict__ stB,
    float* __restrict__ hall, int ctr_idx) {
    __shared__ __nv_bfloat16 sh[IDIM * BATCH];  // [i*8 + b], 16KB
    const int tid = threadIdx.x;
    const int lane = tid & 31;
    const int warp = tid >> 5;
    const int j = (blockIdx.x << 3) + warp;  // 0..1023

    float wreg[32];
#pragma unroll
    for (int q = 0; q < 32; q++) wreg[q] = Wr[j * IDIM + (q << 5) + lane];
    const float bj = bias[j];
    unsigned* ctr = &g_ctr[ctr_idx];

#pragma unroll 1
    for (int t = 0; t < T; t++) {
        const float* src = (t & 1) ? stB : stA;
        float*       dst = (t & 1) ? stA : stB;

        // fill smem with bf16 copy of state; __ldcg: L1 is stale across SMs within a launch
#pragma unroll
        for (int r = 0; r < 8; r++) {
            const int g = (r << 8) + tid;  // 2048 float4 groups
            const float4 v = __ldcg(((const float4*)src) + g);
            __nv_bfloat162* d2 = reinterpret_cast<__nv_bfloat162*>(sh + (g << 2));
            d2[0] = __floats2bfloat162_rn(v.x, v.y);
            d2[1] = __floats2bfloat162_rn(v.z, v.w);
        }
        __syncthreads();

        float acc[8];
#pragma unroll
        for (int b = 0; b < 8; b++) acc[b] = 0.f;

#pragma unroll
        for (int q = 0; q < 32; q++) {
            const float w = wreg[q];
            const int i = (q << 5) + lane;
            const uint4 hv = *reinterpret_cast<const uint4*>(sh + (i << 3));
            const float2 f0 = __bfloat1622float2(*reinterpret_cast<const __nv_bfloat162*>(&hv.x));
            const float2 f1 = __bfloat1622float2(*reinterpret_cast<const __nv_bfloat162*>(&hv.y));
            const float2 f2 = __bfloat1622float2(*reinterpret_cast<const __nv_bfloat162*>(&hv.z));
            const float2 f3 = __bfloat1622float2(*reinterpret_cast<const __nv_bfloat162*>(&hv.w));
            acc[0] += w * f0.x; acc[1] += w * f0.y;
            acc[2] += w * f1.x; acc[3] += w * f1.y;
            acc[4] += w * f2.x; acc[5] += w * f2.y;
            acc[6] += w * f3.x; acc[7] += w * f3.y;
        }

#pragma unroll
        for (int off = 16; off > 0; off >>= 1)
#pragma unroll
            for (int b = 0; b < 8; b++)
                acc[b] += __shfl_xor_sync(0xffffffffu, acc[b], off);

        if (lane < 8) {
            float a = acc[0];
#pragma unroll
            for (int b = 1; b < 8; b++)
                if (lane == b) a = acc[b];
            const size_t m = (size_t)lane * T + t;  // row b*T + t
            const float h = tanhf(U[m * IDIM + j] + a + bj);
            hall[m * IDIM + j] = h;
            dst[(j << 3) + lane] = h;
        }

        // global barrier (monotonic target; counter reset by init_kernel each launch)
        __syncthreads();
        if (tid == 0) {
            __threadfence();
            atomicAdd(ctr, 1u);
            const unsigned tgt = (unsigned)(NBLK * (t + 1));
            volatile unsigned* vc = (volatile unsigned*)ctr;
            while (*vc < tgt) {}
        }
        __syncthreads();
    }
}

// ---------------- launch ----------------
extern "C" void kernel_launch(void* const* d_in, const int* in_sizes, int n_in,
                              void* d_out, int out_size) {
    const float* x       = (const float*)d_in[0];
    const float* w_dw0   = (const float*)d_in[1];
    const float* b_dw0   = (const float*)d_in[2];
    const float* w_dw1   = (const float*)d_in[3];
    const float* b_dw1   = (const float*)d_in[4];
    const float* w_join  = (const float*)d_in[5];
    const float* b_join  = (const float*)d_in[6];
    const float* w_ih0   = (const float*)d_in[7];
    const float* w_hh0   = (const float*)d_in[8];
    const float* b_ih0   = (const float*)d_in[9];
    const float* b_hh0   = (const float*)d_in[10];
    const float* w_ih1   = (const float*)d_in[11];
    const float* w_hh1   = (const float*)d_in[12];
    const float* b_ih1   = (const float*)d_in[13];
    const float* b_hh1   = (const float*)d_in[14];
    const float* w_u1    = (const float*)d_in[15];
    const float* b_u1    = (const float*)d_in[16];
    const float* w_u2    = (const float*)d_in[17];
    const float* b_u2    = (const float*)d_in[18];
    const float* starter = (const float*)d_in[19];
    float* out = (float*)d_out;

    float *hT, *hj, *u0, *hall0, *v1, *hall1, *y1, *y2;
    float *st0a, *st0b, *st1a, *st1b;
    cudaGetSymbolAddress((void**)&hT, g_hT);
    cudaGetSymbolAddress((void**)&hj, g_hj);
    cudaGetSymbolAddress((void**)&u0, g_u0);
    cudaGetSymbolAddress((void**)&hall0, g_hall0);
    cudaGetSymbolAddress((void**)&v1, g_v1);
    cudaGetSymbolAddress((void**)&hall1, g_hall1);
    cudaGetSymbolAddress((void**)&y1, g_y1);
    cudaGetSymbolAddress((void**)&y2, g_y2);
    cudaGetSymbolAddress((void**)&st0a, g_st0a);
    cudaGetSymbolAddress((void**)&st0b, g_st0b);
    cudaGetSymbolAddress((void**)&st1a, g_st1a);
    cudaGetSymbolAddress((void**)&st1b, g_st1b);

    const int elem = BATCH * DIM * T;  // 4,194,304

    init_kernel<<<(IDIM * BATCH + 255) / 256, 256>>>(starter);
    conv0_kernel<<<elem / 256, 256>>>(x, w_dw0, b_dw0);
    // join: [8192,512] x [1024,512]^T
    gemm_nt<<<dim3(IDIM / 128, M_ROWS / 128), 256>>>(hT, w_join, b_join, hj, IDIM, DIM, 0);
    // u0 = hj @ w_ih0^T + b_ih0
    gemm_nt<<<dim3(IDIM / 128, M_ROWS / 128), 256>>>(hj, w_ih0, b_ih0, u0, IDIM, IDIM, 0);
    // chain 0: h0_t = tanh(u0_t + h0 W_hh0^T + b_hh0)
    chain_kernel<<<NBLK, 256>>>(w_hh0, u0, b_hh0, st0a, st0b, hall0, 0);
    // v1 = h0_all @ w_ih1^T + b_ih1
    gemm_nt<<<dim3(IDIM / 128, M_ROWS / 128), 256>>>(hall0, w_ih1, b_ih1, v1, IDIM, IDIM, 0);
    // chain 1: h1_t = tanh(v1_t + h1 W_hh1^T + b_hh1)
    chain_kernel<<<NBLK, 256>>>(w_hh1, v1, b_hh1, st1a, st1b, hall1, 1);
    // unjoin MLP with fused exact-erf gelu
    gemm_nt<<<dim3(IDIM / 128, M_ROWS / 128), 256>>>(hall1, w_u1, b_u1, y1, IDIM, IDIM, 1);
    gemm_nt<<<dim3(DIM / 128, M_ROWS / 128), 256>>>(y1, w_u2, b_u2, y2, DIM, IDIM, 1);
    // final depthwise conv + bias + residual
    conv1_kernel<<<elem / 256, 256>>>(x, w_dw1, b_dw1, out);
}

// round 17
// speedup vs baseline: 1.2719x; 1.2719x over previous
#include <cuda_runtime.h>
#include <cuda_bf16.h>
#include <cstdint>

#define BATCH 8
#define T 1024
#define DIM 512
#define IDIM 1024
#define M_ROWS (BATCH * T)   // 8192
#define NBLK 128             // persistent chain grid (<= SM count, single wave)
#define SST 40               // gemm smem row stride (bf16 elems); 80B -> conflict-free lds
#define NCTR 8               // barrier counters per chain (16 CTAs arrive per counter)
#define CTRPAD 32            // counter padding (words) -> 128B line spacing

// ---------------- scratch (static device globals; no allocation) ----------------
__device__ __align__(16) __nv_bfloat16 g_hT[M_ROWS * DIM];     // conv0 out (bf16)
__device__ __align__(16) __nv_bfloat16 g_hj[M_ROWS * IDIM];    // join out (bf16)
__device__ float g_u0[M_ROWS * IDIM];                          // ih0 proj (fp32, chain U)
__device__ __align__(16) __nv_bfloat16 g_hall0[M_ROWS * IDIM]; // h0 all t (bf16)
__device__ float g_v1[M_ROWS * IDIM];                          // ih1 proj (fp32, chain U)
__device__ __align__(16) __nv_bfloat16 g_hall1[M_ROWS * IDIM]; // h1 all t (bf16)
__device__ __align__(16) __nv_bfloat16 g_y1[M_ROWS * IDIM];    // unjoin mlp1 (bf16)
__device__ float g_y2[M_ROWS * DIM];                           // unjoin mlp2 (fp32)
// bf16 weight copies
__device__ __align__(16) __nv_bfloat16 g_wjoin[IDIM * DIM];
__device__ __align__(16) __nv_bfloat16 g_wih0[IDIM * IDIM];
__device__ __align__(16) __nv_bfloat16 g_wih1[IDIM * IDIM];
__device__ __align__(16) __nv_bfloat16 g_wu1[IDIM * IDIM];
__device__ __align__(16) __nv_bfloat16 g_wu2[DIM * IDIM];
// chain state ping-pong, bf16 ([i*8+b])
__device__ __align__(16) __nv_bfloat16 g_st0a[IDIM * BATCH];
__device__ __align__(16) __nv_bfloat16 g_st0b[IDIM * BATCH];
__device__ __align__(16) __nv_bfloat16 g_st1a[IDIM * BATCH];
__device__ __align__(16) __nv_bfloat16 g_st1b[IDIM * BATCH];
// barrier counters: R6-proven mechanism (atomicAdd + volatile poll), but 8 padded
// counters per chain (one 128B line apart) so arrivals don't serialize on one address
__device__ __align__(128) unsigned g_ctr2[2][NCTR * CTRPAD];

__device__ __forceinline__ float gelu_f(float v) {
    return 0.5f * v * (1.0f + erff(v * 0.70710678118654752f));
}

// fast tanh: 1 - 2/(exp(2x)+1); __expf saturates correctly at both ends
__device__ __forceinline__ float tanh_fast(float x) {
    float e = __expf(2.0f * x);
    return 1.0f - __fdividef(2.0f, e + 1.0f);
}

// ---------------- fp32 -> bf16 weight conversion (n divisible by 1024) ----------------
__global__ void f2bf_kernel(const float* __restrict__ s, __nv_bfloat16* __restrict__ d) {
    const int i = (blockIdx.x * blockDim.x + threadIdx.x) << 2;
    const float4 v = *(const float4*)(s + i);
    __nv_bfloat162* o = (__nv_bfloat162*)(d + i);
    o[0] = __floats2bfloat162_rn(v.x, v.y);
    o[1] = __floats2bfloat162_rn(v.z, v.w);
}

// ---------------- init: reset counters, broadcast starter state (bf16) ----------------
__global__ void init_kernel(const float* __restrict__ starter) {
    int idx = blockIdx.x * blockDim.x + threadIdx.x;
    if (idx < IDIM * BATCH) {
        g_st0a[idx] = __float2bfloat16_rn(starter[idx >> 3]);
        g_st1a[idx] = __float2bfloat16_rn(starter[IDIM + (idx >> 3)]);
    }
    if (idx < 2 * NCTR * CTRPAD) ((unsigned*)g_ctr2)[idx] = 0u;
}

// ---------------- depthwise conv 7 + gelu, write transposed bf16 [b*T+t][d] ----------------
__global__ void conv0_kernel(const float* __restrict__ x,
                             const float* __restrict__ w,
                             const float* __restrict__ bb) {
    const int idx = blockIdx.x * blockDim.x + threadIdx.x;  // (b,d,t), t fastest
    const int t = idx & (T - 1);
    const int d = (idx >> 10) & (DIM - 1);
    const int b = idx >> 19;
    const float* xr = x + ((size_t)(b * DIM + d) << 10);
    const float* wd = w + d * 7;
    float acc = bb[d];
#pragma unroll
    for (int k = 0; k < 7; k++) {
        const int tt = t + k - 3;
        if (tt >= 0 && tt < T) acc += wd[k] * xr[tt];
    }
    g_hT[((size_t)((b << 10) + t)) * DIM + d] = __float2bfloat16_rn(gelu_f(acc));
}

// ---------------- final depthwise conv 7 + bias + residual ----------------
__global__ void conv1_kernel(const float* __restrict__ x,
                             const float* __restrict__ w,
                             const float* __restrict__ bb,
                             float* __restrict__ out) {
    const int idx = blockIdx.x * blockDim.x + threadIdx.x;  // (b,d,t), t fastest
    const int t = idx & (T - 1);
    const int d = (idx >> 10) & (DIM - 1);
    const int b = idx >> 19;
    const float* wd = w + d * 7;
    float acc = bb[d];
#pragma unroll
    for (int k = 0; k < 7; k++) {
        const int tt = t + k - 3;
        if (tt >= 0 && tt < T)
            acc += wd[k] * g_y2[((size_t)((b << 10) + tt)) * DIM + d];
    }
    out[idx] = x[idx] + acc;
}

// ---------------- bf16 tensor-core NT GEMM ----------------
// C[M,N] = act(A[M,K] * W[N,K]^T + bias[N]); A,W bf16 K-major; C fp32 or bf16.
// 128x128 tile, BK=32, 8 warps (4M x 2N), each warp 32x64 via mma.m16n8k16.
#define MMA_BF16(d, a, b0, b1)                                            \
    asm volatile(                                                         \
        "mma.sync.aligned.m16n8k16.row.col.f32.bf16.bf16.f32 "            \
        "{%0,%1,%2,%3}, {%4,%5,%6,%7}, {%8,%9}, {%0,%1,%2,%3};"           \
        : "+f"(d[0]), "+f"(d[1]), "+f"(d[2]), "+f"(d[3])                  \
        : "r"(a[0]), "r"(a[1]), "r"(a[2]), "r"(a[3]), "r"(b0), "r"(b1))

__global__ void __launch_bounds__(256) gemm_bf16(
    const __nv_bfloat16* __restrict__ A, const __nv_bfloat16* __restrict__ W,
    const float* __restrict__ bias, void* __restrict__ Cout,
    int N, int K, int act, int out_bf) {
    __shared__ __nv_bfloat16 As[128 * SST];
    __shared__ __nv_bfloat16 Ws[128 * SST];
    const int tid = threadIdx.x;
    const int lane = tid & 31;
    const int warp = tid >> 5;
    const int wm = (warp >> 1) << 5;   // 0,32,64,96
    const int wn = (warp & 1) << 6;    // 0,64
    const int g = lane >> 2;           // 0..7
    const int tg = lane & 3;           // 0..3
    const size_t row0 = (size_t)blockIdx.y << 7;
    const int col0 = blockIdx.x << 7;
    const int lrow = tid >> 2;         // 0..63 (2 passes cover 128 rows)
    const int lseg = (tid & 3) << 3;   // bf16 offset within 32-elem k-chunk

    float acc[2][8][4];
#pragma unroll
    for (int mt = 0; mt < 2; mt++)
#pragma unroll
        for (int nt = 0; nt < 8; nt++)
#pragma unroll
            for (int c = 0; c < 4; c++) acc[mt][nt][c] = 0.f;

    for (int k0 = 0; k0 < K; k0 += 32) {
#pragma unroll
        for (int p = 0; p < 2; p++) {
            const int r = (p << 6) + lrow;
            *(uint4*)&As[r * SST + lseg] = *(const uint4*)&A[(row0 + r) * K + k0 + lseg];
            *(uint4*)&Ws[r * SST + lseg] = *(const uint4*)&W[(size_t)(col0 + r) * K + k0 + lseg];
        }
        __syncthreads();
#pragma unroll
        for (int ks = 0; ks < 32; ks += 16) {
            uint32_t a[2][4];
#pragma unroll
            for (int mt = 0; mt < 2; mt++) {
                const int rb = (wm + (mt << 4) + g) * SST + ks + (tg << 1);
                a[mt][0] = *(const uint32_t*)&As[rb];
                a[mt][1] = *(const uint32_t*)&As[rb + 8 * SST];
                a[mt][2] = *(const uint32_t*)&As[rb + 8];
                a[mt][3] = *(const uint32_t*)&As[rb + 8 * SST + 8];
            }
#pragma unroll
            for (int nt = 0; nt < 8; nt++) {
                const int cb = (wn + (nt << 3) + g) * SST + ks + (tg << 1);
                const uint32_t b0 = *(const uint32_t*)&Ws[cb];
                const uint32_t b1 = *(const uint32_t*)&Ws[cb + 8];
                MMA_BF16(acc[0][nt], a[0], b0, b1);
                MMA_BF16(acc[1][nt], a[1], b0, b1);
            }
        }
        __syncthreads();
    }

    // epilogue: c0,c1 = row g cols 2tg,2tg+1 ; c2,c3 = row g+8
    float* Cf = (float*)Cout;
    __nv_bfloat16* Cb = (__nv_bfloat16*)Cout;
#pragma unroll
    for (int mt = 0; mt < 2; mt++) {
        const size_t r1 = row0 + wm + (mt << 4) + g;
        const size_t r2 = r1 + 8;
#pragma unroll
        for (int nt = 0; nt < 8; nt++) {
            const int c = col0 + wn + (nt << 3) + (tg << 1);
            const float2 bv = *(const float2*)&bias[c];
            float v00 = acc[mt][nt][0] + bv.x;
            float v01 = acc[mt][nt][1] + bv.y;
            float v10 = acc[mt][nt][2] + bv.x;
            float v11 = acc[mt][nt][3] + bv.y;
            if (act) {
                v00 = gelu_f(v00); v01 = gelu_f(v01);
                v10 = gelu_f(v10); v11 = gelu_f(v11);
            }
            if (out_bf) {
                *(__nv_bfloat162*)&Cb[r1 * N + c] = __floats2bfloat162_rn(v00, v01);
                *(__nv_bfloat162*)&Cb[r2 * N + c] = __floats2bfloat162_rn(v10, v11);
            } else {
                *(float2*)&Cf[r1 * N + c] = make_float2(v00, v01);
                *(float2*)&Cf[r2 * N + c] = make_float2(v10, v11);
            }
        }
    }
}

// ---------------- persistent RNN chain: h_t = tanh(U_t + h_{t-1} * Wr^T + bias) ----------------
// 128 CTAs x 8 warps = 1024 warps; warp g owns output row j, weights in 32 regs.
// State lives in global as bf16 ping-pong; per step each CTA raw-copies 16KB into smem,
// computes, writes its 8 rows of next-state (bf16) + hall (bf16).
// Barrier = the R6-PROVEN mechanism (threadfence + atomicAdd arrival; single-thread
// volatile poll), widened to 8 line-padded counters (16 CTAs each) so arrivals do not
// serialize on one L2 address. Flag-store barriers (R11/R14) hung: plain release
// stores / non-clobber asm polls are orderable by the compiler; atomics are not.
__global__ void __launch_bounds__(256) chain_kernel(
    const float* __restrict__ Wr, const float* __restrict__ U,
    const float* __restrict__ bias,
    __nv_bfloat16* __restrict__ stA, __nv_bfloat16* __restrict__ stB,
    __nv_bfloat16* __restrict__ hall, unsigned* __restrict__ ctr) {
    __shared__ __align__(16) __nv_bfloat16 sh[IDIM * BATCH];  // [i*8 + b], 16KB
    const int tid = threadIdx.x;
    const int lane = tid & 31;
    const int warp = tid >> 5;
    const int j = (blockIdx.x << 3) + warp;  // 0..1023

    float wreg[32];
#pragma unroll
    for (int q = 0; q < 32; q++) wreg[q] = Wr[j * IDIM + (q << 5) + lane];
    const float bj = bias[j];
    unsigned* myctr = &ctr[(blockIdx.x & (NCTR - 1)) * CTRPAD];

#pragma unroll 1
    for (int t = 0; t < T; t++) {
        const __nv_bfloat16* src = (t & 1) ? stB : stA;
        __nv_bfloat16*       dst = (t & 1) ? stA : stB;

        // prefetch U early (DRAM latency hidden behind fill + compute)
        float uf = 0.f;
        if (lane < 8) uf = __ldcg(&U[((size_t)lane * T + t) * IDIM + j]);

        // raw copy of bf16 state into smem; __ldcg: L1 stale across SMs within a launch
        const uint4* srcv = (const uint4*)src;  // 1024 x 16B
#pragma unroll
        for (int r = 0; r < 4; r++) {
            const int g = (r << 8) + tid;
            ((uint4*)sh)[g] = __ldcg(srcv + g);
        }
        __syncthreads();

        float acc[8];
#pragma unroll
        for (int b = 0; b < 8; b++) acc[b] = 0.f;

#pragma unroll
        for (int q = 0; q < 32; q++) {
            const float w = wreg[q];
            const int i = (q << 5) + lane;
            const uint4 hv = *reinterpret_cast<const uint4*>(sh + (i << 3));
            const float2 f0 = __bfloat1622float2(*reinterpret_cast<const __nv_bfloat162*>(&hv.x));
            const float2 f1 = __bfloat1622float2(*reinterpret_cast<const __nv_bfloat162*>(&hv.y));
            const float2 f2 = __bfloat1622float2(*reinterpret_cast<const __nv_bfloat162*>(&hv.z));
            const float2 f3 = __bfloat1622float2(*reinterpret_cast<const __nv_bfloat162*>(&hv.w));
            acc[0] += w * f0.x; acc[1] += w * f0.y;
            acc[2] += w * f1.x; acc[3] += w * f1.y;
            acc[4] += w * f2.x; acc[5] += w * f2.y;
            acc[6] += w * f3.x; acc[7] += w * f3.y;
        }

#pragma unroll
        for (int off = 16; off > 0; off >>= 1)
#pragma unroll
            for (int b = 0; b < 8; b++)
                acc[b] += __shfl_xor_sync(0xffffffffu, acc[b], off);

        if (lane < 8) {
            float a = acc[0];
#pragma unroll
            for (int b = 1; b < 8; b++)
                if (lane == b) a = acc[b];
            const float h = tanh_fast(uf + a + bj);
            const __nv_bfloat16 hb = __float2bfloat16_rn(h);
            hall[((size_t)lane * T + t) * IDIM + j] = hb;
            dst[(j << 3) + lane] = hb;
        }

        // arrival: all CTA writes done -> fence + atomicAdd on this CTA's group counter
        __syncthreads();
        if (tid == 0) {
            __threadfence();
            atomicAdd(myctr, 1u);
            // wait: poll all 8 padded counters (volatile loads; cannot be hoisted)
            const unsigned tgt = (unsigned)((NBLK / NCTR) * (t + 1));
            volatile unsigned* vc = (volatile unsigned*)ctr;
            bool wait = true;
            while (wait) {
                wait = false;
#pragma unroll
                for (int c = 0; c < NCTR; c++)
                    wait |= (vc[c * CTRPAD] < tgt);
            }
            __threadfence();  // acquire: order subsequent state reads after observation
        }
        __syncthreads();
    }
}

// ---------------- launch ----------------
extern "C" void kernel_launch(void* const* d_in, const int* in_sizes, int n_in,
                              void* d_out, int out_size) {
    const float* x       = (const float*)d_in[0];
    const float* w_dw0   = (const float*)d_in[1];
    const float* b_dw0   = (const float*)d_in[2];
    const float* w_dw1   = (const float*)d_in[3];
    const float* b_dw1   = (const float*)d_in[4];
    const float* w_join  = (const float*)d_in[5];
    const float* b_join  = (const float*)d_in[6];
    const float* w_ih0   = (const float*)d_in[7];
    const float* w_hh0   = (const float*)d_in[8];
    const float* b_ih0   = (const float*)d_in[9];
    const float* b_hh0   = (const float*)d_in[10];
    const float* w_ih1   = (const float*)d_in[11];
    const float* w_hh1   = (const float*)d_in[12];
    const float* b_ih1   = (const float*)d_in[13];
    const float* b_hh1   = (const float*)d_in[14];
    const float* w_u1    = (const float*)d_in[15];
    const float* b_u1    = (const float*)d_in[16];
    const float* w_u2    = (const float*)d_in[17];
    const float* b_u2    = (const float*)d_in[18];
    const float* starter = (const float*)d_in[19];
    float* out = (float*)d_out;

    __nv_bfloat16 *hT, *hj, *hall0, *hall1, *y1;
    __nv_bfloat16 *wjoin, *wih0, *wih1, *wu1, *wu2;
    float *u0, *v1, *y2;
    __nv_bfloat16 *st0a, *st0b, *st1a, *st1b;
    unsigned* ctr;
    cudaGetSymbolAddress((void**)&hT, g_hT);
    cudaGetSymbolAddress((void**)&hj, g_hj);
    cudaGetSymbolAddress((void**)&u0, g_u0);
    cudaGetSymbolAddress((void**)&hall0, g_hall0);
    cudaGetSymbolAddress((void**)&v1, g_v1);
    cudaGetSymbolAddress((void**)&hall1, g_hall1);
    cudaGetSymbolAddress((void**)&y1, g_y1);
    cudaGetSymbolAddress((void**)&y2, g_y2);
    cudaGetSymbolAddress((void**)&wjoin, g_wjoin);
    cudaGetSymbolAddress((void**)&wih0, g_wih0);
    cudaGetSymbolAddress((void**)&wih1, g_wih1);
    cudaGetSymbolAddress((void**)&wu1, g_wu1);
    cudaGetSymbolAddress((void**)&wu2, g_wu2);
    cudaGetSymbolAddress((void**)&st0a, g_st0a);
    cudaGetSymbolAddress((void**)&st0b, g_st0b);
    cudaGetSymbolAddress((void**)&st1a, g_st1a);
    cudaGetSymbolAddress((void**)&st1b, g_st1b);
    cudaGetSymbolAddress((void**)&ctr, g_ctr2);

    const int elem = BATCH * DIM * T;  // 4,194,304

    init_kernel<<<(IDIM * BATCH + 255) / 256, 256>>>(starter);
    // weight conversions (fp32 -> bf16), 1024 elems per block
    f2bf_kernel<<<(IDIM * DIM) / 1024, 256>>>(w_join, wjoin);
    f2bf_kernel<<<(IDIM * IDIM) / 1024, 256>>>(w_ih0, wih0);
    f2bf_kernel<<<(IDIM * IDIM) / 1024, 256>>>(w_ih1, wih1);
    f2bf_kernel<<<(IDIM * IDIM) / 1024, 256>>>(w_u1, wu1);
    f2bf_kernel<<<(DIM * IDIM) / 1024, 256>>>(w_u2, wu2);

    conv0_kernel<<<elem / 256, 256>>>(x, w_dw0, b_dw0);
    // join: [8192,512] x [1024,512]^T -> bf16 hj
    gemm_bf16<<<dim3(IDIM / 128, M_ROWS / 128), 256>>>(hT, wjoin, b_join, hj, IDIM, DIM, 0, 1);
    // u0 = hj @ w_ih0^T + b_ih0 -> fp32
    gemm_bf16<<<dim3(IDIM / 128, M_ROWS / 128), 256>>>(hj, wih0, b_ih0, u0, IDIM, IDIM, 0, 0);
    // chain 0: h0_t = tanh(u0_t + h0 W_hh0^T + b_hh0)
    chain_kernel<<<NBLK, 256>>>(w_hh0, u0, b_hh0, st0a, st0b, hall0, ctr);
    // v1 = h0_all @ w_ih1^T + b_ih1 -> fp32
    gemm_bf16<<<dim3(IDIM / 128, M_ROWS / 128), 256>>>(hall0, wih1, b_ih1, v1, IDIM, IDIM, 0, 0);
    // chain 1: h1_t = tanh(v1_t + h1 W_hh1^T + b_hh1)
    chain_kernel<<<NBLK, 256>>>(w_hh1, v1, b_hh1, st1a, st1b, hall1, ctr + NCTR * CTRPAD);
    // unjoin MLP with fused exact-erf gelu
    gemm_bf16<<<dim3(IDIM / 128, M_ROWS / 128), 256>>>(hall1, wu1, b_u1, y1, IDIM, IDIM, 1, 1);
    gemm_bf16<<<dim3(DIM / 128, M_ROWS / 128), 256>>>(y1, wu2, b_u2, y2, DIM, IDIM, 1, 0);
    // final depthwise conv + bias + residual
    conv1_kernel<<<elem / 256, 256>>>(x, w_dw1, b_dw1, out);
}